// round 3
// baseline (speedup 1.0000x reference)
#include <cuda_runtime.h>
#include <cuda_bf16.h>
#include <cstdint>
#include <math.h>

#define NQ    2048
#define DIM   256
#define NF    100000
#define NCLS  1000
#define KSEL  16
#define TAUF  0.2f
#define LSCALE 20.0f

#define BM 128
#define BN 128
#define NSTRIPE 37
#define TPS 22
#define PS (TPS*BN)          // 2816 features per stripe
#define KP 16                // per-row per-stripe candidates
#define NCAND (NSTRIPE*KP)   // 592
#define CSEL 32

// smem layout (bytes, dynamic)
#define SM_A   0                 // 128 x 256 bf16, blocked+swizzled : 65536
#define SM_B   65536             // 2 x (128 x 64 bf16) kc chunks    : 32768
#define SM_S   98304             // 2 x (128 x 136 bf16) sims        : 69632
#define SBUF   34816             // one sims buffer
#define SROW   272               // sims row stride bytes (136 bf16)
#define SM_TOTAL 167936

// named barrier ids
#define BAR_FULL0 1
#define BAR_FULL1 2
#define BAR_EMPTY0 3
#define BAR_EMPTY1 4
#define BAR_COMP 5

// ---------------- device scratch ----------------
__device__ __nv_bfloat16 g_xb[NQ*DIM];
__device__ float         g_xn[NQ*DIM];
__device__ __nv_bfloat16 g_mb[(size_t)NF*DIM];
__device__ float         g_cval[(size_t)NQ*NCAND];
__device__ int           g_cidx[(size_t)NQ*NCAND];

// ---------------- PTX helpers ----------------
__device__ __forceinline__ void cpa16(unsigned dst, const void* src, int sz){
  asm volatile("cp.async.cg.shared.global [%0], [%1], 16, %2;\n"
    :: "r"(dst), "l"(__cvta_generic_to_global(src)), "r"(sz));
}
__device__ __forceinline__ void cpa_commit(){ asm volatile("cp.async.commit_group;\n"); }
template<int N> __device__ __forceinline__ void cpa_wait(){
  asm volatile("cp.async.wait_group %0;\n" :: "n"(N));
}
__device__ __forceinline__ void bar_sync(int id, int cnt){
  asm volatile("bar.sync %0, %1;" :: "r"(id), "r"(cnt) : "memory");
}
__device__ __forceinline__ void bar_arrive(int id, int cnt){
  asm volatile("bar.arrive %0, %1;" :: "r"(id), "r"(cnt) : "memory");
}
__device__ __forceinline__ void ldsm4(uint32_t* r, unsigned addr){
  asm volatile("ldmatrix.sync.aligned.m8n8.x4.shared.b16 {%0,%1,%2,%3}, [%4];\n"
    : "=r"(r[0]), "=r"(r[1]), "=r"(r[2]), "=r"(r[3]) : "r"(addr));
}
__device__ __forceinline__ void mma16816(float* d, const uint32_t* a, uint32_t b0, uint32_t b1){
  asm volatile(
    "mma.sync.aligned.m16n8k16.row.col.f32.bf16.bf16.f32 "
    "{%0,%1,%2,%3}, {%4,%5,%6,%7}, {%8,%9}, {%0,%1,%2,%3};\n"
    : "+f"(d[0]), "+f"(d[1]), "+f"(d[2]), "+f"(d[3])
    : "r"(a[0]), "r"(a[1]), "r"(a[2]), "r"(a[3]), "r"(b0), "r"(b1));
}

// ---------------- kernel 1: setup = bf16 convert + standardize/normalize ----------------
__global__ void setup_kernel(const float* __restrict__ x, const float* __restrict__ mean,
                             const float* __restrict__ stdv, const float* __restrict__ mf){
  {
    int stride = gridDim.x * blockDim.x;
    int n4 = NF*DIM/4;
    for (int i = blockIdx.x*blockDim.x + threadIdx.x; i < n4; i += stride){
      float4 f = ((const float4*)mf)[i];
      __nv_bfloat162* o = (__nv_bfloat162*)g_mb;
      o[2*i]   = __floats2bfloat162_rn(f.x, f.y);
      o[2*i+1] = __floats2bfloat162_rn(f.z, f.w);
    }
  }
  int r = blockIdx.x, t = threadIdx.x;
  float v = (x[r*DIM + t] - mean[t]) / stdv[t];
  float s = v*v;
  #pragma unroll
  for (int o = 16; o; o >>= 1) s += __shfl_xor_sync(0xffffffffu, s, o);
  __shared__ float ws[8];
  __shared__ float nrm;
  if ((t & 31) == 0) ws[t >> 5] = s;
  __syncthreads();
  if (t == 0){
    float tot = 0.f;
    #pragma unroll
    for (int i = 0; i < 8; i++) tot += ws[i];
    nrm = fmaxf(sqrtf(tot), 1e-6f);
  }
  __syncthreads();
  float o = v / nrm;
  g_xn[r*DIM + t] = o;
  g_xb[r*DIM + t] = __float2bfloat16(o);
}

// ---------------- kernel 2: warp-specialized mma.sync GEMM + overlapped top-k ----------------
__device__ __forceinline__ void load_B_chunk(unsigned sB_u, int buf, int nb, int kc, int t){
  unsigned bbase = sB_u + (unsigned)buf * 16384u;
  #pragma unroll
  for (int i = 0; i < 4; i++){
    int id = t + 256*i;
    int r = id >> 3, c = id & 7;
    int fr = nb + r;
    int ok = (fr < NF);
    cpa16(bbase + (unsigned)((r*8 + ((c ^ r) & 7)) * 16),
          g_mb + (size_t)(ok ? fr : 0) * DIM + kc*64 + c*8, ok ? 16 : 0);
  }
}

__global__ void __launch_bounds__(384, 1) gemm_topk_kernel(){
  extern __shared__ char smem[];
  const unsigned sA_u = (unsigned)__cvta_generic_to_shared(smem);
  const unsigned sB_u = sA_u + SM_B - 0 + 0 + (SM_B - SM_B); // keep simple below
  const unsigned sBu  = sA_u + SM_B;
  const unsigned sSu  = sA_u + SM_S;

  int t = threadIdx.x, lane = t & 31, w = t >> 5;
  int m0 = blockIdx.x * BM;
  int sb = blockIdx.y * PS;
  int rem = NF - sb;
  int ntiles = (rem <= 0) ? 0 : ((rem >= PS) ? TPS : ((rem + BN - 1) / BN));

  if (ntiles == 0){
    if (w >= 8){
      int row = t - 256;
      size_t base = (size_t)(m0 + row) * NCAND + (size_t)blockIdx.y * KP;
      #pragma unroll
      for (int i = 0; i < KP; i++){ g_cval[base + i] = -INFINITY; g_cidx[base + i] = 0; }
    }
    return;
  }

  if (w < 8){
    // ================= compute warps =================
    // load A tile [128 x 256] (blocked swizzled), + B tile0 chunk0
    #pragma unroll
    for (int i = 0; i < 16; i++){
      int id = t + 256*i;
      int row = id >> 5, c = id & 31;
      int phys = (c & 24) | ((c ^ row) & 7);
      cpa16(sA_u + (unsigned)((row*32 + phys)*16),
            g_xb + (size_t)(m0 + row)*DIM + c*8, 16);
    }
    load_B_chunk(sBu, 0, sb, 0, t);
    cpa_commit();

    int wr = (w >> 2) * 64;
    int wc = (w & 3) * 32;
    int buf = 0;

    for (int i = 0; i < ntiles; i++){
      float acc[4][4][4];
      #pragma unroll
      for (int mf = 0; mf < 4; mf++)
        #pragma unroll
        for (int nf = 0; nf < 4; nf++)
          #pragma unroll
          for (int q = 0; q < 4; q++) acc[mf][nf][q] = 0.f;

      #pragma unroll
      for (int kc = 0; kc < 4; kc++){
        bar_sync(BAR_COMP, 256);           // all compute done reading buf^1 (prev stage)
        int ni = i, nk = kc + 1;
        if (nk == 4){ nk = 0; ni = i + 1; }
        if (ni < ntiles) load_B_chunk(sBu, buf ^ 1, sb + ni*BN, nk, t);
        cpa_commit();
        cpa_wait<1>();                      // data for buf arrived (this thread's share)
        bar_sync(BAR_COMP, 256);           // everyone's share arrived

        unsigned bbase = sBu + (unsigned)buf * 16384u;
        #pragma unroll
        for (int s = 0; s < 4; s++){
          int c0 = kc*8 + 2*s;
          uint32_t af[4][4];
          #pragma unroll
          for (int mf = 0; mf < 4; mf++){
            int row = wr + 16*mf + (lane & 15);
            int c = c0 + (lane >> 4);
            int phys = (c & 24) | ((c ^ row) & 7);
            ldsm4(af[mf], sA_u + (unsigned)((row*32 + phys)*16));
          }
          uint32_t b0v[4], b1v[4];
          #pragma unroll
          for (int p = 0; p < 2; p++){
            int row = wc + 16*p + (lane & 15);
            int c = 2*s + (lane >> 4);
            int phys = (c ^ row) & 7;
            uint32_t r[4];
            ldsm4(r, bbase + (unsigned)((row*8 + phys)*16));
            b0v[2*p] = r[0]; b0v[2*p+1] = r[1]; b1v[2*p] = r[2]; b1v[2*p+1] = r[3];
          }
          #pragma unroll
          for (int mf = 0; mf < 4; mf++)
            #pragma unroll
            for (int nf = 0; nf < 4; nf++)
              mma16816(acc[mf][nf], af[mf], b0v[nf], b1v[nf]);
        }
        buf ^= 1;
      }

      // dump sims tile (bf16) into sims buffer b = i&1
      int b = i & 1;
      bar_sync(BAR_EMPTY0 + b, 384);        // scanner done with old contents
      unsigned sdst = sSu + (unsigned)b * SBUF;
      int r0r = wr + (lane >> 2);
      int c0c = wc + 2*(lane & 3);
      #pragma unroll
      for (int mf = 0; mf < 4; mf++){
        #pragma unroll
        for (int nf = 0; nf < 4; nf++){
          int rr = r0r + 16*mf, cc = c0c + 8*nf;
          __nv_bfloat162 p0 = __floats2bfloat162_rn(acc[mf][nf][0], acc[mf][nf][1]);
          __nv_bfloat162 p1 = __floats2bfloat162_rn(acc[mf][nf][2], acc[mf][nf][3]);
          *(__nv_bfloat162*)(smem + SM_S + b*SBUF + rr*SROW + cc*2) = p0;
          *(__nv_bfloat162*)(smem + SM_S + b*SBUF + (rr+8)*SROW + cc*2) = p1;
        }
      }
      __threadfence_block();
      bar_arrive(BAR_FULL0 + b, 384);
      (void)sdst;
    }
  } else {
    // ================= scanner warps =================
    int row = t - 256;
    float tv[KP]; int ti[KP];
    #pragma unroll
    for (int i = 0; i < KP; i++){ tv[i] = -INFINITY; ti[i] = 0; }
    float tmin = -INFINITY; int minpos = 0;

    bar_arrive(BAR_EMPTY0, 384);
    bar_arrive(BAR_EMPTY1, 384);

    for (int i = 0; i < ntiles; i++){
      int b = i & 1;
      bar_sync(BAR_FULL0 + b, 384);
      const uint4* src = (const uint4*)(smem + SM_S + b*SBUF + row*SROW);
      int nb = sb + i * BN;
      #pragma unroll
      for (int v = 0; v < 16; v++){
        uint4 d = src[v];
        uint32_t word[4] = {d.x, d.y, d.z, d.w};
        #pragma unroll
        for (int h = 0; h < 4; h++){
          float2 f = __bfloat1622float2(*(__nv_bfloat162*)&word[h]);
          int gc0 = nb + v*8 + 2*h;
          if (f.x > tmin && gc0 < NF){
            #pragma unroll
            for (int q = 0; q < KP; q++) if (q == minpos){ tv[q] = f.x; ti[q] = gc0; }
            tmin = tv[0]; minpos = 0;
            #pragma unroll
            for (int q = 1; q < KP; q++) if (tv[q] < tmin){ tmin = tv[q]; minpos = q; }
          }
          if (f.y > tmin && gc0 + 1 < NF){
            #pragma unroll
            for (int q = 0; q < KP; q++) if (q == minpos){ tv[q] = f.y; ti[q] = gc0 + 1; }
            tmin = tv[0]; minpos = 0;
            #pragma unroll
            for (int q = 1; q < KP; q++) if (tv[q] < tmin){ tmin = tv[q]; minpos = q; }
          }
        }
      }
      bar_arrive(BAR_EMPTY0 + b, 384);
    }

    size_t base = (size_t)(m0 + row) * NCAND + (size_t)blockIdx.y * KP;
    #pragma unroll
    for (int i = 0; i < KP; i++){ g_cval[base + i] = tv[i]; g_cidx[base + i] = ti[i]; }
  }
}

// ---------------- kernel 3: merge + exact rescore + softmax + scatter ----------------
__global__ void __launch_bounds__(128) merge_kernel(const float* __restrict__ mf,
                                                    const int* __restrict__ lab,
                                                    float* __restrict__ out){
  int row = blockIdx.x, t = threadIdx.x, lane = t & 31, w = t >> 5;
  __shared__ float cv[NCAND];
  __shared__ int   ci[NCAND];
  __shared__ float xs[DIM];
  __shared__ float accs[NCLS];
  __shared__ int   selIdx[CSEL];
  __shared__ float ex[CSEL];
  __shared__ float wgt[KSEL]; __shared__ int flab[KSEL];

  for (int j = t; j < NCAND; j += 128){
    cv[j] = g_cval[(size_t)row*NCAND + j];
    ci[j] = g_cidx[(size_t)row*NCAND + j];
  }
  for (int j = t; j < DIM; j += 128) xs[j] = g_xn[row*DIM + j];
  for (int c = t; c < NCLS; c += 128) accs[c] = 0.f;
  __syncthreads();

  if (w == 0){
    for (int it = 0; it < CSEL; it++){
      float bv = -INFINITY; int bp = 0;
      for (int j = lane; j < NCAND; j += 32){
        float c = cv[j];
        if (c > bv){ bv = c; bp = j; }
      }
      #pragma unroll
      for (int o = 16; o; o >>= 1){
        float ov = __shfl_xor_sync(0xffffffffu, bv, o);
        int   op = __shfl_xor_sync(0xffffffffu, bp, o);
        if (ov > bv || (ov == bv && op < bp)){ bv = ov; bp = op; }
      }
      if (lane == 0){ selIdx[it] = ci[bp]; cv[bp] = -INFINITY; }
      __syncwarp();
    }
  }
  __syncthreads();

  for (int rr = 0; rr < CSEL/4; rr++){
    int c = w + 4*rr;
    const float* fr = mf + (size_t)selIdx[c] * DIM;
    float s = 0.f;
    #pragma unroll
    for (int j = 0; j < 8; j++){ int k = lane + 32*j; s += fr[k] * xs[k]; }
    #pragma unroll
    for (int o = 16; o; o >>= 1) s += __shfl_down_sync(0xffffffffu, s, o);
    if (lane == 0) ex[c] = s;
  }
  __syncthreads();

  if (t == 0){
    unsigned um = 0;
    float sval[KSEL]; int sfeat[KSEL];
    for (int it = 0; it < KSEL; it++){
      float bv = -INFINITY; int bc = 0;
      for (int c = 0; c < CSEL; c++){
        if (!((um >> c) & 1u) && ex[c] > bv){ bv = ex[c]; bc = c; }
      }
      um |= 1u << bc;
      sval[it] = bv; sfeat[it] = selIdx[bc];
    }
    float m = sval[0], sum = 0.f;
    for (int i = 0; i < KSEL; i++){ float e = expf((sval[i]-m)/TAUF); wgt[i] = e; sum += e; }
    float inv = 1.f / sum;
    for (int i = 0; i < KSEL; i++){ wgt[i] *= inv; flab[i] = lab[sfeat[i]]; }
    for (int i = 0; i < KSEL; i++) accs[flab[i]] += wgt[i];
  }
  __syncthreads();
  for (int c = t; c < NCLS; c += 128) out[(size_t)row*NCLS + c] = accs[c] * LSCALE;
}

// ---------------- kernel 4: dummy (ncu launch alignment) ----------------
__global__ void dummy_kernel(){}

// ---------------- launch ----------------
extern "C" void kernel_launch(void* const* d_in, const int* in_sizes, int n_in,
                              void* d_out, int out_size){
  const float* x    = (const float*)d_in[0];
  const float* mean = (const float*)d_in[1];
  const float* stdv = (const float*)d_in[2];
  const float* mf   = (const float*)d_in[3];
  const int*   lab  = (const int*)d_in[4];
  float* out = (float*)d_out;

  cudaFuncSetAttribute(gemm_topk_kernel, cudaFuncAttributeMaxDynamicSharedMemorySize, SM_TOTAL);

  setup_kernel<<<NQ, DIM>>>(x, mean, stdv, mf);
  gemm_topk_kernel<<<dim3(NQ/BM, NSTRIPE), 384, SM_TOTAL>>>();
  merge_kernel<<<NQ, 128>>>(mf, lab, out);
  dummy_kernel<<<1, 32>>>();
}

// round 4
// speedup vs baseline: 3.0086x; 3.0086x over previous
#include <cuda_runtime.h>
#include <cuda_bf16.h>
#include <cstdint>
#include <math.h>

#define NQ    2048
#define DIM   256
#define NF    100000
#define NCLS  1000
#define KSEL  16
#define TAUF  0.2f
#define LSCALE 20.0f

#define BM 128
#define BN 128
#define NSTRIPE 37
#define TT 782               // total column tiles = ceil(100000/128)
#define TBASE 21             // tiles per stripe (first 5 stripes get +1)
#define KP 8                 // per (row, col-half) candidates per stripe
#define NCAND (NSTRIPE*2*KP) // 592
#define CSEL 32

// smem layout (bytes, dynamic)
#define SM_A   0                 // 128 x 256 bf16 blocked+swizzled : 65536
#define SM_B   65536             // ring of 4 x (128 x 64 bf16)     : 65536
#define SM_S   131072            // 2 x (128 x 136 bf16) sims       : 69632
#define SBUF   34816
#define SROW   272
#define SM_TOTAL 200704

// ---------------- device scratch ----------------
__device__ __nv_bfloat16 g_xb[NQ*DIM];
__device__ float         g_xn[NQ*DIM];
__device__ __nv_bfloat16 g_mb[(size_t)NF*DIM];
__device__ float         g_cval[(size_t)NQ*NCAND];
__device__ int           g_cidx[(size_t)NQ*NCAND];

// ---------------- PTX helpers ----------------
__device__ __forceinline__ void cpa16(unsigned dst, const void* src, int sz){
  asm volatile("cp.async.cg.shared.global [%0], [%1], 16, %2;\n"
    :: "r"(dst), "l"(__cvta_generic_to_global(src)), "r"(sz));
}
__device__ __forceinline__ void cpa_commit(){ asm volatile("cp.async.commit_group;\n"); }
template<int N> __device__ __forceinline__ void cpa_wait(){
  asm volatile("cp.async.wait_group %0;\n" :: "n"(N));
}
__device__ __forceinline__ void ldsm4(uint32_t* r, unsigned addr){
  asm volatile("ldmatrix.sync.aligned.m8n8.x4.shared.b16 {%0,%1,%2,%3}, [%4];\n"
    : "=r"(r[0]), "=r"(r[1]), "=r"(r[2]), "=r"(r[3]) : "r"(addr));
}
__device__ __forceinline__ void mma16816(float* d, const uint32_t* a, uint32_t b0, uint32_t b1){
  asm volatile(
    "mma.sync.aligned.m16n8k16.row.col.f32.bf16.bf16.f32 "
    "{%0,%1,%2,%3}, {%4,%5,%6,%7}, {%8,%9}, {%0,%1,%2,%3};\n"
    : "+f"(d[0]), "+f"(d[1]), "+f"(d[2]), "+f"(d[3])
    : "r"(a[0]), "r"(a[1]), "r"(a[2]), "r"(a[3]), "r"(b0), "r"(b1));
}

// ---------------- kernel 1: setup ----------------
__global__ void setup_kernel(const float* __restrict__ x, const float* __restrict__ mean,
                             const float* __restrict__ stdv, const float* __restrict__ mf){
  {
    int stride = gridDim.x * blockDim.x;
    int n4 = NF*DIM/4;
    for (int i = blockIdx.x*blockDim.x + threadIdx.x; i < n4; i += stride){
      float4 f = ((const float4*)mf)[i];
      __nv_bfloat162* o = (__nv_bfloat162*)g_mb;
      o[2*i]   = __floats2bfloat162_rn(f.x, f.y);
      o[2*i+1] = __floats2bfloat162_rn(f.z, f.w);
    }
  }
  int r = blockIdx.x, t = threadIdx.x;
  float v = (x[r*DIM + t] - mean[t]) / stdv[t];
  float s = v*v;
  #pragma unroll
  for (int o = 16; o; o >>= 1) s += __shfl_xor_sync(0xffffffffu, s, o);
  __shared__ float ws[8];
  __shared__ float nrm;
  if ((t & 31) == 0) ws[t >> 5] = s;
  __syncthreads();
  if (t == 0){
    float tot = 0.f;
    #pragma unroll
    for (int i = 0; i < 8; i++) tot += ws[i];
    nrm = fmaxf(sqrtf(tot), 1e-6f);
  }
  __syncthreads();
  float o = v / nrm;
  g_xn[r*DIM + t] = o;
  g_xb[r*DIM + t] = __float2bfloat16(o);
}

// ---------------- kernel 2: GEMM + interleaved top-k ----------------
__device__ __forceinline__ void load_B_chunk(unsigned sBu, int buf, int nb, int kc, int t){
  unsigned bbase = sBu + (unsigned)buf * 16384u;
  #pragma unroll
  for (int i = 0; i < 4; i++){
    int id = t + 256*i;
    int r = id >> 3, c = id & 7;
    int fr = nb + r;
    int ok = (fr < NF);
    cpa16(bbase + (unsigned)((r*8 + ((c ^ r) & 7)) * 16),
          g_mb + (size_t)(ok ? fr : 0) * DIM + kc*64 + c*8, ok ? 16 : 0);
  }
}

__global__ void __launch_bounds__(256, 1) gemm_topk_kernel(){
  extern __shared__ char smem[];
  const unsigned sA_u = (unsigned)__cvta_generic_to_shared(smem);
  const unsigned sBu  = sA_u + SM_B;

  int t = threadIdx.x, lane = t & 31, w = t >> 5;
  int m0 = blockIdx.x * BM;
  int y  = blockIdx.y;
  int t0 = y * TBASE + min(y, 5);
  int ntiles = TBASE + (y < 5 ? 1 : 0);

  // per-thread scan identity: 2 threads per row, 64 cols each
  int srow = t & 127;
  int sch  = t >> 7;

  float tv[KP]; int ti[KP];
  #pragma unroll
  for (int i = 0; i < KP; i++){ tv[i] = -INFINITY; ti[i] = 0; }
  float tmin = -INFINITY; int minpos = 0;

  // scan one 16-col chunk of the sims buffer pb for tile whose col base is nb
  auto scan_chunk = [&](int pb, int nb, int kc){
    const uint4* src = (const uint4*)(smem + SM_S + pb*SBUF + srow*SROW + sch*128 + kc*32);
    #pragma unroll
    for (int v = 0; v < 2; v++){
      uint4 d = src[v];
      uint32_t word[4] = {d.x, d.y, d.z, d.w};
      #pragma unroll
      for (int h = 0; h < 4; h++){
        float2 f = __bfloat1622float2(*(__nv_bfloat162*)&word[h]);
        int gc0 = nb + sch*64 + kc*16 + v*8 + 2*h;
        if (f.x > tmin && gc0 < NF){
          #pragma unroll
          for (int q = 0; q < KP; q++) if (q == minpos){ tv[q] = f.x; ti[q] = gc0; }
          tmin = tv[0]; minpos = 0;
          #pragma unroll
          for (int q = 1; q < KP; q++) if (tv[q] < tmin){ tmin = tv[q]; minpos = q; }
        }
        if (f.y > tmin && gc0 + 1 < NF){
          #pragma unroll
          for (int q = 0; q < KP; q++) if (q == minpos){ tv[q] = f.y; ti[q] = gc0 + 1; }
          tmin = tv[0]; minpos = 0;
          #pragma unroll
          for (int q = 1; q < KP; q++) if (tv[q] < tmin){ tmin = tv[q]; minpos = q; }
        }
      }
    }
  };

  // prologue: A tile + first 3 B stages (each its own cp.async group)
  #pragma unroll
  for (int i = 0; i < 16; i++){
    int id = t + 256*i;
    int row = id >> 5, c = id & 31;
    int phys = (c & 24) | ((c ^ row) & 7);
    cpa16(sA_u + (unsigned)((row*32 + phys)*16),
          g_xb + (size_t)(m0 + row)*DIM + c*8, 16);
  }
  load_B_chunk(sBu, 0, (t0 + 0)*BN, 0, t);
  cpa_commit();
  load_B_chunk(sBu, 1, (t0 + 0)*BN, 1, t);
  cpa_commit();
  load_B_chunk(sBu, 2, (t0 + 0)*BN, 2, t);
  cpa_commit();

  int wr = (w >> 2) * 64;
  int wc = (w & 3) * 32;
  int total = ntiles * 4;

  for (int i = 0; i < ntiles; i++){
    float acc[4][4][4];
    #pragma unroll
    for (int mf = 0; mf < 4; mf++)
      #pragma unroll
      for (int nf = 0; nf < 4; nf++)
        #pragma unroll
        for (int q = 0; q < 4; q++) acc[mf][nf][q] = 0.f;

    #pragma unroll
    for (int kc = 0; kc < 4; kc++){
      int s = i*4 + kc;
      __syncthreads();                    // everyone done reading buf[(s+3)&3]'s old data
      int sn = s + 3;
      if (sn < total){
        load_B_chunk(sBu, sn & 3, (t0 + (sn >> 2))*BN, sn & 3 ? (sn & 3) : 0, t);
      }
      cpa_commit();
      cpa_wait<3>();
      __syncthreads();                    // buf[s&3] fully arrived (all threads' shares)

      unsigned bbase = sBu + (unsigned)(s & 3) * 16384u;
      #pragma unroll
      for (int ss = 0; ss < 4; ss++){
        int c0 = kc*8 + 2*ss;
        uint32_t af[4][4];
        #pragma unroll
        for (int mf = 0; mf < 4; mf++){
          int row = wr + 16*mf + (lane & 15);
          int c = c0 + (lane >> 4);
          int phys = (c & 24) | ((c ^ row) & 7);
          ldsm4(af[mf], sA_u + (unsigned)((row*32 + phys)*16));
        }
        uint32_t b0v[4], b1v[4];
        #pragma unroll
        for (int p = 0; p < 2; p++){
          int row = wc + 16*p + (lane & 15);
          int c = 2*ss + (lane >> 4);
          int phys = (c ^ row) & 7;
          uint32_t r[4];
          ldsm4(r, bbase + (unsigned)((row*8 + phys)*16));
          b0v[2*p] = r[0]; b0v[2*p+1] = r[1]; b1v[2*p] = r[2]; b1v[2*p+1] = r[3];
        }
        #pragma unroll
        for (int mf = 0; mf < 4; mf++)
          #pragma unroll
          for (int nf = 0; nf < 4; nf++)
            mma16816(acc[mf][nf], af[mf], b0v[nf], b1v[nf]);
      }

      // interleaved scan: chunk kc of previous tile's sims
      if (i > 0) scan_chunk((i - 1) & 1, (t0 + i - 1)*BN, kc);
    }

    // dump sims tile i (bf16) into buffer i&1
    int b = i & 1;
    int r0r = wr + (lane >> 2);
    int c0c = wc + 2*(lane & 3);
    #pragma unroll
    for (int mf = 0; mf < 4; mf++){
      #pragma unroll
      for (int nf = 0; nf < 4; nf++){
        int rr = r0r + 16*mf, cc = c0c + 8*nf;
        __nv_bfloat162 p0 = __floats2bfloat162_rn(acc[mf][nf][0], acc[mf][nf][1]);
        __nv_bfloat162 p1 = __floats2bfloat162_rn(acc[mf][nf][2], acc[mf][nf][3]);
        *(__nv_bfloat162*)(smem + SM_S + b*SBUF + rr*SROW + cc*2) = p0;
        *(__nv_bfloat162*)(smem + SM_S + b*SBUF + (rr+8)*SROW + cc*2) = p1;
      }
    }
  }

  // epilogue: scan last tile
  __syncthreads();
  {
    int i = ntiles - 1;
    #pragma unroll
    for (int kc = 0; kc < 4; kc++) scan_chunk(i & 1, (t0 + i)*BN, kc);
  }

  size_t base = (size_t)(m0 + srow) * NCAND + (size_t)y * (2*KP) + (size_t)sch * KP;
  #pragma unroll
  for (int i = 0; i < KP; i++){ g_cval[base + i] = tv[i]; g_cidx[base + i] = ti[i]; }
}

// ---------------- kernel 3: merge + exact rescore + softmax + scatter ----------------
__global__ void __launch_bounds__(128) merge_kernel(const float* __restrict__ mf,
                                                    const int* __restrict__ lab,
                                                    float* __restrict__ out){
  int row = blockIdx.x, t = threadIdx.x, lane = t & 31, w = t >> 5;
  __shared__ float cv[NCAND];
  __shared__ int   ci[NCAND];
  __shared__ float xs[DIM];
  __shared__ float accs[NCLS];
  __shared__ int   selIdx[CSEL];
  __shared__ float ex[CSEL];
  __shared__ float wgt[KSEL]; __shared__ int flab[KSEL];

  for (int j = t; j < NCAND; j += 128){
    cv[j] = g_cval[(size_t)row*NCAND + j];
    ci[j] = g_cidx[(size_t)row*NCAND + j];
  }
  for (int j = t; j < DIM; j += 128) xs[j] = g_xn[row*DIM + j];
  for (int c = t; c < NCLS; c += 128) accs[c] = 0.f;
  __syncthreads();

  if (w == 0){
    for (int it = 0; it < CSEL; it++){
      float bv = -INFINITY; int bp = 0;
      for (int j = lane; j < NCAND; j += 32){
        float c = cv[j];
        if (c > bv){ bv = c; bp = j; }
      }
      #pragma unroll
      for (int o = 16; o; o >>= 1){
        float ov = __shfl_xor_sync(0xffffffffu, bv, o);
        int   op = __shfl_xor_sync(0xffffffffu, bp, o);
        if (ov > bv || (ov == bv && op < bp)){ bv = ov; bp = op; }
      }
      if (lane == 0){ selIdx[it] = ci[bp]; cv[bp] = -INFINITY; }
      __syncwarp();
    }
  }
  __syncthreads();

  for (int rr = 0; rr < CSEL/4; rr++){
    int c = w + 4*rr;
    const float* fr = mf + (size_t)selIdx[c] * DIM;
    float s = 0.f;
    #pragma unroll
    for (int j = 0; j < 8; j++){ int k = lane + 32*j; s += fr[k] * xs[k]; }
    #pragma unroll
    for (int o = 16; o; o >>= 1) s += __shfl_down_sync(0xffffffffu, s, o);
    if (lane == 0) ex[c] = s;
  }
  __syncthreads();

  if (t == 0){
    unsigned um = 0;
    float sval[KSEL]; int sfeat[KSEL];
    for (int it = 0; it < KSEL; it++){
      float bv = -INFINITY; int bc = 0;
      for (int c = 0; c < CSEL; c++){
        if (!((um >> c) & 1u) && ex[c] > bv){ bv = ex[c]; bc = c; }
      }
      um |= 1u << bc;
      sval[it] = bv; sfeat[it] = selIdx[bc];
    }
    float m = sval[0], sum = 0.f;
    for (int i = 0; i < KSEL; i++){ float e = expf((sval[i]-m)/TAUF); wgt[i] = e; sum += e; }
    float inv = 1.f / sum;
    for (int i = 0; i < KSEL; i++){ wgt[i] *= inv; flab[i] = lab[sfeat[i]]; }
    for (int i = 0; i < KSEL; i++) accs[flab[i]] += wgt[i];
  }
  __syncthreads();
  for (int c = t; c < NCLS; c += 128) out[(size_t)row*NCLS + c] = accs[c] * LSCALE;
}

// ---------------- dummy (profiling alignment: gemm at launch position 3) ----------------
__global__ void dummy_kernel(){}

// ---------------- launch ----------------
extern "C" void kernel_launch(void* const* d_in, const int* in_sizes, int n_in,
                              void* d_out, int out_size){
  const float* x    = (const float*)d_in[0];
  const float* mean = (const float*)d_in[1];
  const float* stdv = (const float*)d_in[2];
  const float* mf   = (const float*)d_in[3];
  const int*   lab  = (const int*)d_in[4];
  float* out = (float*)d_out;

  cudaFuncSetAttribute(gemm_topk_kernel, cudaFuncAttributeMaxDynamicSharedMemorySize, SM_TOTAL);

  setup_kernel<<<NQ, DIM>>>(x, mean, stdv, mf);   // pos 0
  dummy_kernel<<<1, 32>>>();                      // pos 1
  dummy_kernel<<<1, 32>>>();                      // pos 2
  gemm_topk_kernel<<<dim3(NQ/BM, NSTRIPE), 256, SM_TOTAL>>>();  // pos 3
  merge_kernel<<<NQ, 128>>>(mf, lab, out);        // pos 4
}

// round 5
// speedup vs baseline: 5.1516x; 1.7123x over previous
#include <cuda_runtime.h>
#include <cuda_bf16.h>
#include <cstdint>
#include <math.h>

#define NQ    2048
#define DIM   256
#define NF    100000
#define NCLS  1000
#define KSEL  16
#define TAUF  0.2f
#define LSCALE 20.0f

#define BM 128
#define BN 128
#define NSTRIPE 37
#define TBASE 21             // tiles per stripe (first 5 stripes get +1)
#define KP 8                 // per (row, col-quarter) candidates per stripe
#define NCAND (NSTRIPE*4*KP) // 1184
#define CSEL 32

#define NT 512               // threads per CTA (16 warps)

// smem layout (bytes, dynamic)
#define SM_A   0                 // 128 x 256 bf16 blocked+swizzled : 65536
#define SM_B   65536             // ring of 4 x (128 x 64 bf16)     : 65536
#define SM_S   131072            // 2 x (128 x 136 bf16) sims       : 69632
#define SBUF   34816
#define SROW   272
#define SM_TOTAL 200704

// ---------------- device scratch ----------------
__device__ __nv_bfloat16 g_xb[NQ*DIM];
__device__ float         g_xn[NQ*DIM];
__device__ __nv_bfloat16 g_mb[(size_t)NF*DIM];
__device__ float         g_cval[(size_t)NQ*NCAND];
__device__ int           g_cidx[(size_t)NQ*NCAND];

// ---------------- PTX helpers ----------------
__device__ __forceinline__ void cpa16(unsigned dst, const void* src, int sz){
  asm volatile("cp.async.cg.shared.global [%0], [%1], 16, %2;\n"
    :: "r"(dst), "l"(__cvta_generic_to_global(src)), "r"(sz));
}
__device__ __forceinline__ void cpa_commit(){ asm volatile("cp.async.commit_group;\n"); }
template<int N> __device__ __forceinline__ void cpa_wait(){
  asm volatile("cp.async.wait_group %0;\n" :: "n"(N));
}
__device__ __forceinline__ void ldsm4(uint32_t* r, unsigned addr){
  asm volatile("ldmatrix.sync.aligned.m8n8.x4.shared.b16 {%0,%1,%2,%3}, [%4];\n"
    : "=r"(r[0]), "=r"(r[1]), "=r"(r[2]), "=r"(r[3]) : "r"(addr));
}
__device__ __forceinline__ void mma16816(float* d, const uint32_t* a, uint32_t b0, uint32_t b1){
  asm volatile(
    "mma.sync.aligned.m16n8k16.row.col.f32.bf16.bf16.f32 "
    "{%0,%1,%2,%3}, {%4,%5,%6,%7}, {%8,%9}, {%0,%1,%2,%3};\n"
    : "+f"(d[0]), "+f"(d[1]), "+f"(d[2]), "+f"(d[3])
    : "r"(a[0]), "r"(a[1]), "r"(a[2]), "r"(a[3]), "r"(b0), "r"(b1));
}

// ---------------- kernel 1: setup ----------------
__global__ void setup_kernel(const float* __restrict__ x, const float* __restrict__ mean,
                             const float* __restrict__ stdv, const float* __restrict__ mf){
  {
    int stride = gridDim.x * blockDim.x;
    int n4 = NF*DIM/4;
    for (int i = blockIdx.x*blockDim.x + threadIdx.x; i < n4; i += stride){
      float4 f = ((const float4*)mf)[i];
      __nv_bfloat162* o = (__nv_bfloat162*)g_mb;
      o[2*i]   = __floats2bfloat162_rn(f.x, f.y);
      o[2*i+1] = __floats2bfloat162_rn(f.z, f.w);
    }
  }
  int r = blockIdx.x, t = threadIdx.x;
  float v = (x[r*DIM + t] - mean[t]) / stdv[t];
  float s = v*v;
  #pragma unroll
  for (int o = 16; o; o >>= 1) s += __shfl_xor_sync(0xffffffffu, s, o);
  __shared__ float ws[8];
  __shared__ float nrm;
  if ((t & 31) == 0) ws[t >> 5] = s;
  __syncthreads();
  if (t == 0){
    float tot = 0.f;
    #pragma unroll
    for (int i = 0; i < 8; i++) tot += ws[i];
    nrm = fmaxf(sqrtf(tot), 1e-6f);
  }
  __syncthreads();
  float o = v / nrm;
  g_xn[r*DIM + t] = o;
  g_xb[r*DIM + t] = __float2bfloat16(o);
}

// ---------------- kernel 2: GEMM + interleaved top-k (512 threads) ----------------
__device__ __forceinline__ void load_B_chunk(unsigned sBu, int buf, int nb, int kc, int t){
  unsigned bbase = sBu + (unsigned)buf * 16384u;
  #pragma unroll
  for (int i = 0; i < 2; i++){
    int id = t + NT*i;
    int r = id >> 3, c = id & 7;
    int fr = nb + r;
    int ok = (fr < NF);
    cpa16(bbase + (unsigned)((r*8 + ((c ^ r) & 7)) * 16),
          g_mb + (size_t)(ok ? fr : 0) * DIM + kc*64 + c*8, ok ? 16 : 0);
  }
}

__global__ void __launch_bounds__(NT, 1) gemm_topk_kernel(){
  extern __shared__ char smem[];
  const unsigned sA_u = (unsigned)__cvta_generic_to_shared(smem);
  const unsigned sBu  = sA_u + SM_B;

  int t = threadIdx.x, lane = t & 31, w = t >> 5;
  int m0 = blockIdx.x * BM;
  int y  = blockIdx.y;
  int t0 = y * TBASE + min(y, 5);
  int ntiles = TBASE + (y < 5 ? 1 : 0);

  // scan identity: 4 threads per row, 32 cols each
  int srow = t & 127;
  int squad = t >> 7;

  float tv[KP]; int ti[KP];
  #pragma unroll
  for (int i = 0; i < KP; i++){ tv[i] = -INFINITY; ti[i] = 0; }
  float tmin = -INFINITY; int minpos = 0;

  // scan one 8-col chunk (one uint4) of sims buffer pb, tile col base nb
  auto scan_chunk = [&](int pb, int nb, int kc){
    uint4 d = *(const uint4*)(smem + SM_S + pb*SBUF + srow*SROW + squad*64 + kc*16);
    uint32_t word[4] = {d.x, d.y, d.z, d.w};
    #pragma unroll
    for (int h = 0; h < 4; h++){
      float2 f = __bfloat1622float2(*(__nv_bfloat162*)&word[h]);
      int gc0 = nb + squad*32 + kc*8 + 2*h;
      if (f.x > tmin && gc0 < NF){
        #pragma unroll
        for (int q = 0; q < KP; q++) if (q == minpos){ tv[q] = f.x; ti[q] = gc0; }
        tmin = tv[0]; minpos = 0;
        #pragma unroll
        for (int q = 1; q < KP; q++) if (tv[q] < tmin){ tmin = tv[q]; minpos = q; }
      }
      if (f.y > tmin && gc0 + 1 < NF){
        #pragma unroll
        for (int q = 0; q < KP; q++) if (q == minpos){ tv[q] = f.y; ti[q] = gc0 + 1; }
        tmin = tv[0]; minpos = 0;
        #pragma unroll
        for (int q = 1; q < KP; q++) if (tv[q] < tmin){ tmin = tv[q]; minpos = q; }
      }
    }
  };

  // prologue: A tile + first 3 B stages
  #pragma unroll
  for (int i = 0; i < 8; i++){
    int id = t + NT*i;
    int row = id >> 5, c = id & 31;
    int phys = (c & 24) | ((c ^ row) & 7);
    cpa16(sA_u + (unsigned)((row*32 + phys)*16),
          g_xb + (size_t)(m0 + row)*DIM + c*8, 16);
  }
  load_B_chunk(sBu, 0, (t0 + 0)*BN, 0, t);
  cpa_commit();
  load_B_chunk(sBu, 1, (t0 + 0)*BN, 1, t);
  cpa_commit();
  load_B_chunk(sBu, 2, (t0 + 0)*BN, 2, t);
  cpa_commit();

  int wr = (w >> 2) * 32;     // warp rows [wr, wr+32)
  int wc = (w & 3) * 32;      // warp cols [wc, wc+32)
  int total = ntiles * 4;

  for (int i = 0; i < ntiles; i++){
    float acc[2][4][4];
    #pragma unroll
    for (int mf = 0; mf < 2; mf++)
      #pragma unroll
      for (int nf = 0; nf < 4; nf++)
        #pragma unroll
        for (int q = 0; q < 4; q++) acc[mf][nf][q] = 0.f;

    #pragma unroll
    for (int kc = 0; kc < 4; kc++){
      int s = i*4 + kc;
      __syncthreads();                    // readers of buf[(s+3)&3]'s old data done
      int sn = s + 3;
      if (sn < total){
        load_B_chunk(sBu, sn & 3, (t0 + (sn >> 2))*BN, sn & 3, t);
      }
      cpa_commit();
      cpa_wait<3>();
      __syncthreads();                    // buf[s&3] fully arrived

      unsigned bbase = sBu + (unsigned)(s & 3) * 16384u;
      #pragma unroll
      for (int ss = 0; ss < 4; ss++){
        int c0 = kc*8 + 2*ss;
        uint32_t af[2][4];
        #pragma unroll
        for (int mf = 0; mf < 2; mf++){
          int row = wr + 16*mf + (lane & 15);
          int c = c0 + (lane >> 4);
          int phys = (c & 24) | ((c ^ row) & 7);
          ldsm4(af[mf], sA_u + (unsigned)((row*32 + phys)*16));
        }
        uint32_t b0v[4], b1v[4];
        #pragma unroll
        for (int p = 0; p < 2; p++){
          int row = wc + 16*p + (lane & 15);
          int c = 2*ss + (lane >> 4);
          int phys = (c ^ row) & 7;
          uint32_t r[4];
          ldsm4(r, bbase + (unsigned)((row*8 + phys)*16));
          b0v[2*p] = r[0]; b0v[2*p+1] = r[1]; b1v[2*p] = r[2]; b1v[2*p+1] = r[3];
        }
        #pragma unroll
        for (int mf = 0; mf < 2; mf++)
          #pragma unroll
          for (int nf = 0; nf < 4; nf++)
            mma16816(acc[mf][nf], af[mf], b0v[nf], b1v[nf]);
      }

      // interleaved scan: one uint4 chunk of previous tile's sims
      if (i > 0) scan_chunk((i - 1) & 1, (t0 + i - 1)*BN, kc);
    }

    // dump sims tile i (bf16) into buffer i&1
    int b = i & 1;
    int r0r = wr + (lane >> 2);
    int c0c = wc + 2*(lane & 3);
    #pragma unroll
    for (int mf = 0; mf < 2; mf++){
      #pragma unroll
      for (int nf = 0; nf < 4; nf++){
        int rr = r0r + 16*mf, cc = c0c + 8*nf;
        __nv_bfloat162 p0 = __floats2bfloat162_rn(acc[mf][nf][0], acc[mf][nf][1]);
        __nv_bfloat162 p1 = __floats2bfloat162_rn(acc[mf][nf][2], acc[mf][nf][3]);
        *(__nv_bfloat162*)(smem + SM_S + b*SBUF + rr*SROW + cc*2) = p0;
        *(__nv_bfloat162*)(smem + SM_S + b*SBUF + (rr+8)*SROW + cc*2) = p1;
      }
    }
  }

  // epilogue: scan last tile
  __syncthreads();
  {
    int i = ntiles - 1;
    #pragma unroll
    for (int kc = 0; kc < 4; kc++) scan_chunk(i & 1, (t0 + i)*BN, kc);
  }

  size_t base = (size_t)(m0 + srow) * NCAND + (size_t)y * (4*KP) + (size_t)squad * KP;
  #pragma unroll
  for (int i = 0; i < KP; i++){ g_cval[base + i] = tv[i]; g_cidx[base + i] = ti[i]; }
}

// ---------------- kernel 3: merge + exact rescore + softmax + scatter ----------------
__global__ void __launch_bounds__(128) merge_kernel(const float* __restrict__ mf,
                                                    const int* __restrict__ lab,
                                                    float* __restrict__ out){
  int row = blockIdx.x, t = threadIdx.x, lane = t & 31, w = t >> 5;
  __shared__ float cv[NCAND];
  __shared__ int   ci[NCAND];
  __shared__ float xs[DIM];
  __shared__ float accs[NCLS];
  __shared__ int   selIdx[CSEL];
  __shared__ float ex[CSEL];
  __shared__ float wgt[KSEL]; __shared__ int flab[KSEL];

  for (int j = t; j < NCAND; j += 128){
    cv[j] = g_cval[(size_t)row*NCAND + j];
    ci[j] = g_cidx[(size_t)row*NCAND + j];
  }
  for (int j = t; j < DIM; j += 128) xs[j] = g_xn[row*DIM + j];
  for (int c = t; c < NCLS; c += 128) accs[c] = 0.f;
  __syncthreads();

  if (w == 0){
    for (int it = 0; it < CSEL; it++){
      float bv = -INFINITY; int bp = 0;
      for (int j = lane; j < NCAND; j += 32){
        float c = cv[j];
        if (c > bv){ bv = c; bp = j; }
      }
      #pragma unroll
      for (int o = 16; o; o >>= 1){
        float ov = __shfl_xor_sync(0xffffffffu, bv, o);
        int   op = __shfl_xor_sync(0xffffffffu, bp, o);
        if (ov > bv || (ov == bv && op < bp)){ bv = ov; bp = op; }
      }
      if (lane == 0){ selIdx[it] = ci[bp]; cv[bp] = -INFINITY; }
      __syncwarp();
    }
  }
  __syncthreads();

  for (int rr = 0; rr < CSEL/4; rr++){
    int c = w + 4*rr;
    const float* fr = mf + (size_t)selIdx[c] * DIM;
    float s = 0.f;
    #pragma unroll
    for (int j = 0; j < 8; j++){ int k = lane + 32*j; s += fr[k] * xs[k]; }
    #pragma unroll
    for (int o = 16; o; o >>= 1) s += __shfl_down_sync(0xffffffffu, s, o);
    if (lane == 0) ex[c] = s;
  }
  __syncthreads();

  if (t == 0){
    unsigned um = 0;
    float sval[KSEL]; int sfeat[KSEL];
    for (int it = 0; it < KSEL; it++){
      float bv = -INFINITY; int bc = 0;
      for (int c = 0; c < CSEL; c++){
        if (!((um >> c) & 1u) && ex[c] > bv){ bv = ex[c]; bc = c; }
      }
      um |= 1u << bc;
      sval[it] = bv; sfeat[it] = selIdx[bc];
    }
    float m = sval[0], sum = 0.f;
    for (int i = 0; i < KSEL; i++){ float e = expf((sval[i]-m)/TAUF); wgt[i] = e; sum += e; }
    float inv = 1.f / sum;
    for (int i = 0; i < KSEL; i++){ wgt[i] *= inv; flab[i] = lab[sfeat[i]]; }
    for (int i = 0; i < KSEL; i++) accs[flab[i]] += wgt[i];
  }
  __syncthreads();
  for (int c = t; c < NCLS; c += 128) out[(size_t)row*NCLS + c] = accs[c] * LSCALE;
}

// ---------------- dummy (profiling alignment: gemm at launch position 3) ----------------
__global__ void dummy_kernel(){}

// ---------------- launch ----------------
extern "C" void kernel_launch(void* const* d_in, const int* in_sizes, int n_in,
                              void* d_out, int out_size){
  const float* x    = (const float*)d_in[0];
  const float* mean = (const float*)d_in[1];
  const float* stdv = (const float*)d_in[2];
  const float* mf   = (const float*)d_in[3];
  const int*   lab  = (const int*)d_in[4];
  float* out = (float*)d_out;

  cudaFuncSetAttribute(gemm_topk_kernel, cudaFuncAttributeMaxDynamicSharedMemorySize, SM_TOTAL);

  setup_kernel<<<NQ, DIM>>>(x, mean, stdv, mf);   // pos 0
  dummy_kernel<<<1, 32>>>();                      // pos 1
  dummy_kernel<<<1, 32>>>();                      // pos 2
  gemm_topk_kernel<<<dim3(NQ/BM, NSTRIPE), NT, SM_TOTAL>>>();  // pos 3
  merge_kernel<<<NQ, 128>>>(mf, lab, out);        // pos 4
}

// round 7
// speedup vs baseline: 5.2067x; 1.0107x over previous
#include <cuda_runtime.h>
#include <cuda_bf16.h>
#include <cstdint>
#include <math.h>

#define NQ    2048
#define DIM   256
#define NF    100000
#define NCLS  1000
#define KSEL  16
#define TAUF  0.2f
#define LSCALE 20.0f

#define BM 128
#define BN 128
#define NSTRIPE 37
#define TBASE 21             // tiles per stripe (first 5 stripes get +1)
#define KP 8                 // per (row, col-quarter) candidates per stripe
#define NCAND (NSTRIPE*4*KP) // 1184
#define CSEL 32

#define NT 512               // threads per CTA (16 warps)

// smem layout (bytes, dynamic)
#define SM_A   0                 // 128 x 256 bf16 blocked+swizzled : 65536
#define SM_B   65536             // ring of 4 x (128 x 64 bf16)     : 65536
#define SM_S   131072            // 2 x (128 x 136 bf16) sims       : 69632
#define SBUF   34816
#define SROW   272
#define SM_TOTAL 200704

// ---------------- device scratch ----------------
__device__ __nv_bfloat16 g_xb[NQ*DIM];
__device__ float         g_xn[NQ*DIM];
__device__ __nv_bfloat16 g_mb[(size_t)NF*DIM];
__device__ float         g_cval[(size_t)NQ*NCAND];
__device__ int           g_cidx[(size_t)NQ*NCAND];

// ---------------- PTX helpers ----------------
__device__ __forceinline__ void cpa16(unsigned dst, const void* src, int sz){
  asm volatile("cp.async.cg.shared.global [%0], [%1], 16, %2;\n"
    :: "r"(dst), "l"(__cvta_generic_to_global(src)), "r"(sz));
}
__device__ __forceinline__ void cpa_commit(){ asm volatile("cp.async.commit_group;\n"); }
template<int N> __device__ __forceinline__ void cpa_wait(){
  asm volatile("cp.async.wait_group %0;\n" :: "n"(N));
}
__device__ __forceinline__ void ldsm4(uint32_t* r, unsigned addr){
  asm volatile("ldmatrix.sync.aligned.m8n8.x4.shared.b16 {%0,%1,%2,%3}, [%4];\n"
    : "=r"(r[0]), "=r"(r[1]), "=r"(r[2]), "=r"(r[3]) : "r"(addr));
}
__device__ __forceinline__ void mma16816(float* d, const uint32_t* a, uint32_t b0, uint32_t b1){
  asm volatile(
    "mma.sync.aligned.m16n8k16.row.col.f32.bf16.bf16.f32 "
    "{%0,%1,%2,%3}, {%4,%5,%6,%7}, {%8,%9}, {%0,%1,%2,%3};\n"
    : "+f"(d[0]), "+f"(d[1]), "+f"(d[2]), "+f"(d[3])
    : "r"(a[0]), "r"(a[1]), "r"(a[2]), "r"(a[3]), "r"(b0), "r"(b1));
}

// ---------------- kernel 1: setup ----------------
__global__ void setup_kernel(const float* __restrict__ x, const float* __restrict__ mean,
                             const float* __restrict__ stdv, const float* __restrict__ mf){
  {
    int stride = gridDim.x * blockDim.x;
    int n4 = NF*DIM/4;
    for (int i = blockIdx.x*blockDim.x + threadIdx.x; i < n4; i += stride){
      float4 f = ((const float4*)mf)[i];
      __nv_bfloat162* o = (__nv_bfloat162*)g_mb;
      o[2*i]   = __floats2bfloat162_rn(f.x, f.y);
      o[2*i+1] = __floats2bfloat162_rn(f.z, f.w);
    }
  }
  int r = blockIdx.x, t = threadIdx.x;
  float v = (x[r*DIM + t] - mean[t]) / stdv[t];
  float s = v*v;
  #pragma unroll
  for (int o = 16; o; o >>= 1) s += __shfl_xor_sync(0xffffffffu, s, o);
  __shared__ float ws[8];
  __shared__ float nrm;
  if ((t & 31) == 0) ws[t >> 5] = s;
  __syncthreads();
  if (t == 0){
    float tot = 0.f;
    #pragma unroll
    for (int i = 0; i < 8; i++) tot += ws[i];
    nrm = fmaxf(sqrtf(tot), 1e-6f);
  }
  __syncthreads();
  float o = v / nrm;
  g_xn[r*DIM + t] = o;
  g_xb[r*DIM + t] = __float2bfloat16(o);
}

// ---------------- kernel 2: GEMM + interleaved top-k (512 threads) ----------------
__device__ __forceinline__ void load_B_chunk(unsigned sBu, int buf, int nb, int kc, int t){
  unsigned bbase = sBu + (unsigned)buf * 16384u;
  #pragma unroll
  for (int i = 0; i < 2; i++){
    int id = t + NT*i;
    int r = id >> 3, c = id & 7;
    int fr = nb + r;
    int ok = (fr < NF);
    cpa16(bbase + (unsigned)((r*8 + ((c ^ r) & 7)) * 16),
          g_mb + (size_t)(ok ? fr : 0) * DIM + kc*64 + c*8, ok ? 16 : 0);
  }
}

__global__ void __launch_bounds__(NT, 1) gemm_topk_kernel(){
  extern __shared__ char smem[];
  const unsigned sA_u = (unsigned)__cvta_generic_to_shared(smem);
  const unsigned sBu  = sA_u + SM_B;

  int t = threadIdx.x, lane = t & 31, w = t >> 5;
  int m0 = blockIdx.x * BM;
  int y  = blockIdx.y;
  int t0 = y * TBASE + min(y, 5);
  int ntiles = TBASE + (y < 5 ? 1 : 0);

  // scan identity: 4 threads per row, 32 cols each
  int srow = t & 127;
  int squad = t >> 7;

  float tv[KP]; int ti[KP];
  #pragma unroll
  for (int i = 0; i < KP; i++){ tv[i] = -INFINITY; ti[i] = 0; }
  float tmin = -INFINITY; int minpos = 0;

  // scan one 8-col chunk (one uint4) with hmax2 fast-reject
  auto scan_chunk = [&](int pb, int nb, int kc){
    uint4 d = *(const uint4*)(smem + SM_S + pb*SBUF + srow*SROW + squad*64 + kc*16);
    __nv_bfloat162 v0 = *(__nv_bfloat162*)&d.x;
    __nv_bfloat162 v1 = *(__nv_bfloat162*)&d.y;
    __nv_bfloat162 v2 = *(__nv_bfloat162*)&d.z;
    __nv_bfloat162 v3 = *(__nv_bfloat162*)&d.w;
    __nv_bfloat162 mm = __hmax2(__hmax2(v0, v1), __hmax2(v2, v3));
    float mx = __bfloat162float(__hmax(mm.x, mm.y));
    if (mx > tmin){
      uint32_t word[4] = {d.x, d.y, d.z, d.w};
      int cbase = nb + squad*32 + kc*8;
      #pragma unroll
      for (int h = 0; h < 4; h++){
        float2 f = __bfloat1622float2(*(__nv_bfloat162*)&word[h]);
        int gc0 = cbase + 2*h;
        if (f.x > tmin && gc0 < NF){
          #pragma unroll
          for (int q = 0; q < KP; q++) if (q == minpos){ tv[q] = f.x; ti[q] = gc0; }
          tmin = tv[0]; minpos = 0;
          #pragma unroll
          for (int q = 1; q < KP; q++) if (tv[q] < tmin){ tmin = tv[q]; minpos = q; }
        }
        if (f.y > tmin && gc0 + 1 < NF){
          #pragma unroll
          for (int q = 0; q < KP; q++) if (q == minpos){ tv[q] = f.y; ti[q] = gc0 + 1; }
          tmin = tv[0]; minpos = 0;
          #pragma unroll
          for (int q = 1; q < KP; q++) if (tv[q] < tmin){ tmin = tv[q]; minpos = q; }
        }
      }
    }
  };

  // prologue: A tile + first 3 B stages
  #pragma unroll
  for (int i = 0; i < 8; i++){
    int id = t + NT*i;
    int row = id >> 5, c = id & 31;
    int phys = (c & 24) | ((c ^ row) & 7);
    cpa16(sA_u + (unsigned)((row*32 + phys)*16),
          g_xb + (size_t)(m0 + row)*DIM + c*8, 16);
  }
  load_B_chunk(sBu, 0, (t0 + 0)*BN, 0, t);
  cpa_commit();
  load_B_chunk(sBu, 1, (t0 + 0)*BN, 1, t);
  cpa_commit();
  load_B_chunk(sBu, 2, (t0 + 0)*BN, 2, t);
  cpa_commit();

  int wr = (w >> 2) * 32;     // warp rows [wr, wr+32)
  int wc = (w & 3) * 32;      // warp cols [wc, wc+32)
  int total = ntiles * 4;

  // precompute B smem offsets (kc-invariant): boff[ss][p]
  unsigned boff[4][2];
  #pragma unroll
  for (int ss = 0; ss < 4; ss++){
    #pragma unroll
    for (int p = 0; p < 2; p++){
      int row = wc + 16*p + (lane & 15);
      int c = 2*ss + (lane >> 4);
      int phys = (c ^ row) & 7;
      boff[ss][p] = (unsigned)((row*8 + phys)*16);
    }
  }
  // precompute A row bases
  unsigned arow[2];
  #pragma unroll
  for (int mf = 0; mf < 2; mf++) arow[mf] = (unsigned)(wr + 16*mf + (lane & 15));

  for (int i = 0; i < ntiles; i++){
    float acc[2][4][4];
    #pragma unroll
    for (int mf = 0; mf < 2; mf++)
      #pragma unroll
      for (int nf = 0; nf < 4; nf++)
        #pragma unroll
        for (int q = 0; q < 4; q++) acc[mf][nf][q] = 0.f;

    #pragma unroll
    for (int kc = 0; kc < 4; kc++){
      int s = i*4 + kc;
      cpa_wait<2>();                      // my groups for stage s complete
      __syncthreads();                    // all threads' stage-s data visible; stage s-1 readers done
      int sn = s + 3;
      if (sn < total){
        load_B_chunk(sBu, sn & 3, (t0 + (sn >> 2))*BN, sn & 3, t);
      }
      cpa_commit();

      unsigned bbase = sBu + (unsigned)(s & 3) * 16384u;
      #pragma unroll
      for (int ss = 0; ss < 4; ss++){
        int c0 = kc*8 + 2*ss;
        uint32_t af[2][4];
        #pragma unroll
        for (int mf = 0; mf < 2; mf++){
          int row = arow[mf];
          int c = c0 + (lane >> 4);
          int phys = (c & 24) | ((c ^ row) & 7);
          ldsm4(af[mf], sA_u + (unsigned)((row*32 + phys)*16));
        }
        uint32_t b0v[4], b1v[4];
        #pragma unroll
        for (int p = 0; p < 2; p++){
          uint32_t r[4];
          ldsm4(r, bbase + boff[ss][p]);
          b0v[2*p] = r[0]; b0v[2*p+1] = r[1]; b1v[2*p] = r[2]; b1v[2*p+1] = r[3];
        }
        #pragma unroll
        for (int mf = 0; mf < 2; mf++)
          #pragma unroll
          for (int nf = 0; nf < 4; nf++)
            mma16816(acc[mf][nf], af[mf], b0v[nf], b1v[nf]);
      }

      // interleaved scan: one uint4 chunk of previous tile's sims
      if (i > 0) scan_chunk((i - 1) & 1, (t0 + i - 1)*BN, kc);
    }

    // dump sims tile i (bf16) into buffer i&1
    int b = i & 1;
    int r0r = wr + (lane >> 2);
    int c0c = wc + 2*(lane & 3);
    #pragma unroll
    for (int mf = 0; mf < 2; mf++){
      #pragma unroll
      for (int nf = 0; nf < 4; nf++){
        int rr = r0r + 16*mf, cc = c0c + 8*nf;
        __nv_bfloat162 p0 = __floats2bfloat162_rn(acc[mf][nf][0], acc[mf][nf][1]);
        __nv_bfloat162 p1 = __floats2bfloat162_rn(acc[mf][nf][2], acc[mf][nf][3]);
        *(__nv_bfloat162*)(smem + SM_S + b*SBUF + rr*SROW + cc*2) = p0;
        *(__nv_bfloat162*)(smem + SM_S + b*SBUF + (rr+8)*SROW + cc*2) = p1;
      }
    }
  }

  // epilogue: scan last tile (dump must be visible)
  __syncthreads();
  {
    int i = ntiles - 1;
    #pragma unroll
    for (int kc = 0; kc < 4; kc++) scan_chunk(i & 1, (t0 + i)*BN, kc);
  }

  size_t base = (size_t)(m0 + srow) * NCAND + (size_t)y * (4*KP) + (size_t)squad * KP;
  #pragma unroll
  for (int i = 0; i < KP; i++){ g_cval[base + i] = tv[i]; g_cidx[base + i] = ti[i]; }
}

// ---------------- kernel 3: merge + exact rescore + softmax + scatter ----------------
__global__ void __launch_bounds__(128) merge_kernel(const float* __restrict__ mf,
                                                    const int* __restrict__ lab,
                                                    float* __restrict__ out){
  int row = blockIdx.x, t = threadIdx.x, lane = t & 31, w = t >> 5;
  __shared__ float cv[NCAND];
  __shared__ int   ci[NCAND];
  __shared__ float xs[DIM];
  __shared__ float accs[NCLS];
  __shared__ int   selIdx[CSEL];
  __shared__ float ex[CSEL];
  __shared__ float wgt[KSEL]; __shared__ int flab[KSEL];

  for (int j = t; j < NCAND; j += 128){
    cv[j] = g_cval[(size_t)row*NCAND + j];
    ci[j] = g_cidx[(size_t)row*NCAND + j];
  }
  for (int j = t; j < DIM; j += 128) xs[j] = g_xn[row*DIM + j];
  for (int c = t; c < NCLS; c += 128) accs[c] = 0.f;
  __syncthreads();

  if (w == 0){
    for (int it = 0; it < CSEL; it++){
      float bv = -INFINITY; int bp = 0;
      for (int j = lane; j < NCAND; j += 32){
        float c = cv[j];
        if (c > bv){ bv = c; bp = j; }
      }
      #pragma unroll
      for (int o = 16; o; o >>= 1){
        float ov = __shfl_xor_sync(0xffffffffu, bv, o);
        int   op = __shfl_xor_sync(0xffffffffu, bp, o);
        if (ov > bv || (ov == bv && op < bp)){ bv = ov; bp = op; }
      }
      if (lane == 0){ selIdx[it] = ci[bp]; cv[bp] = -INFINITY; }
      __syncwarp();
    }
  }
  __syncthreads();

  for (int rr = 0; rr < CSEL/4; rr++){
    int c = w + 4*rr;
    const float* fr = mf + (size_t)selIdx[c] * DIM;
    float s = 0.f;
    #pragma unroll
    for (int j = 0; j < 8; j++){ int k = lane + 32*j; s += fr[k] * xs[k]; }
    #pragma unroll
    for (int o = 16; o; o >>= 1) s += __shfl_down_sync(0xffffffffu, s, o);
    if (lane == 0) ex[c] = s;
  }
  __syncthreads();

  if (t == 0){
    unsigned um = 0;
    float sval[KSEL]; int sfeat[KSEL];
    for (int it = 0; it < KSEL; it++){
      float bv = -INFINITY; int bc = 0;
      for (int c = 0; c < CSEL; c++){
        if (!((um >> c) & 1u) && ex[c] > bv){ bv = ex[c]; bc = c; }
      }
      um |= 1u << bc;
      sval[it] = bv; sfeat[it] = selIdx[bc];
    }
    float m = sval[0], sum = 0.f;
    for (int i = 0; i < KSEL; i++){ float e = expf((sval[i]-m)/TAUF); wgt[i] = e; sum += e; }
    float inv = 1.f / sum;
    for (int i = 0; i < KSEL; i++){ wgt[i] *= inv; flab[i] = lab[sfeat[i]]; }
    for (int i = 0; i < KSEL; i++) accs[flab[i]] += wgt[i];
  }
  __syncthreads();
  for (int c = t; c < NCLS; c += 128) out[(size_t)row*NCLS + c] = accs[c] * LSCALE;
}

// ---------------- dummy (profiling alignment: gemm at launch position 3) ----------------
__global__ void dummy_kernel(){}

// ---------------- launch ----------------
extern "C" void kernel_launch(void* const* d_in, const int* in_sizes, int n_in,
                              void* d_out, int out_size){
  const float* x    = (const float*)d_in[0];
  const float* mean = (const float*)d_in[1];
  const float* stdv = (const float*)d_in[2];
  const float* mf   = (const float*)d_in[3];
  const int*   lab  = (const int*)d_in[4];
  float* out = (float*)d_out;

  cudaFuncSetAttribute(gemm_topk_kernel, cudaFuncAttributeMaxDynamicSharedMemorySize, SM_TOTAL);

  setup_kernel<<<NQ, DIM>>>(x, mean, stdv, mf);   // pos 0
  dummy_kernel<<<1, 32>>>();                      // pos 1
  dummy_kernel<<<1, 32>>>();                      // pos 2
  gemm_topk_kernel<<<dim3(NQ/BM, NSTRIPE), NT, SM_TOTAL>>>();  // pos 3
  merge_kernel<<<NQ, 128>>>(mf, lab, out);        // pos 4
}

// round 8
// speedup vs baseline: 5.3097x; 1.0198x over previous
#include <cuda_runtime.h>
#include <cuda_bf16.h>
#include <cstdint>
#include <math.h>

#define NQ    2048
#define DIM   256
#define NF    100000
#define NCLS  1000
#define KSEL  16
#define TAUF  0.2f
#define LSCALE 20.0f

#define BM 128
#define BN 128
#define NSTRIPE 37
#define TBASE 21             // tiles per stripe (first 5 stripes get +1)
#define KP 8                 // per (row, col-quarter) candidates per stripe
#define NCAND (NSTRIPE*4*KP) // 1184
#define CSEL 32

#define NT 512               // threads per CTA (16 warps)

// smem layout (bytes, dynamic)
#define SM_A   0                 // 128 x 256 bf16 blocked+swizzled : 65536
#define SM_B   65536             // ring of 4 x (128 x 64 bf16)     : 65536
#define SM_S   131072            // 2 x (128 x 136 bf16) sims       : 69632
#define SBUF   34816
#define SROW   272
#define SM_TOTAL 200704

// ---------------- device scratch ----------------
__device__ __nv_bfloat16 g_xb[NQ*DIM];
__device__ float         g_xn[NQ*DIM];
__device__ __nv_bfloat16 g_mb[(size_t)NF*DIM];
__device__ float         g_cval[(size_t)NQ*NCAND];
__device__ int           g_cidx[(size_t)NQ*NCAND];

// ---------------- PTX helpers ----------------
__device__ __forceinline__ void cpa16(unsigned dst, const void* src, int sz){
  asm volatile("cp.async.cg.shared.global [%0], [%1], 16, %2;\n"
    :: "r"(dst), "l"(__cvta_generic_to_global(src)), "r"(sz));
}
__device__ __forceinline__ void cpa_commit(){ asm volatile("cp.async.commit_group;\n"); }
template<int N> __device__ __forceinline__ void cpa_wait(){
  asm volatile("cp.async.wait_group %0;\n" :: "n"(N));
}
__device__ __forceinline__ void ldsm4(uint32_t* r, unsigned addr){
  asm volatile("ldmatrix.sync.aligned.m8n8.x4.shared.b16 {%0,%1,%2,%3}, [%4];\n"
    : "=r"(r[0]), "=r"(r[1]), "=r"(r[2]), "=r"(r[3]) : "r"(addr));
}
__device__ __forceinline__ void mma16816(float* d, const uint32_t* a, uint32_t b0, uint32_t b1){
  asm volatile(
    "mma.sync.aligned.m16n8k16.row.col.f32.bf16.bf16.f32 "
    "{%0,%1,%2,%3}, {%4,%5,%6,%7}, {%8,%9}, {%0,%1,%2,%3};\n"
    : "+f"(d[0]), "+f"(d[1]), "+f"(d[2]), "+f"(d[3])
    : "r"(a[0]), "r"(a[1]), "r"(a[2]), "r"(a[3]), "r"(b0), "r"(b1));
}

// ---------------- kernel 1: setup ----------------
__global__ void setup_kernel(const float* __restrict__ x, const float* __restrict__ mean,
                             const float* __restrict__ stdv, const float* __restrict__ mf){
  {
    int stride = gridDim.x * blockDim.x;
    int n4 = NF*DIM/4;
    for (int i = blockIdx.x*blockDim.x + threadIdx.x; i < n4; i += stride){
      float4 f = ((const float4*)mf)[i];
      __nv_bfloat162* o = (__nv_bfloat162*)g_mb;
      o[2*i]   = __floats2bfloat162_rn(f.x, f.y);
      o[2*i+1] = __floats2bfloat162_rn(f.z, f.w);
    }
  }
  int r = blockIdx.x, t = threadIdx.x;
  float v = (x[r*DIM + t] - mean[t]) / stdv[t];
  float s = v*v;
  #pragma unroll
  for (int o = 16; o; o >>= 1) s += __shfl_xor_sync(0xffffffffu, s, o);
  __shared__ float ws[8];
  __shared__ float nrm;
  if ((t & 31) == 0) ws[t >> 5] = s;
  __syncthreads();
  if (t == 0){
    float tot = 0.f;
    #pragma unroll
    for (int i = 0; i < 8; i++) tot += ws[i];
    nrm = fmaxf(sqrtf(tot), 1e-6f);
  }
  __syncthreads();
  float o = v / nrm;
  g_xn[r*DIM + t] = o;
  g_xb[r*DIM + t] = __float2bfloat16(o);
}

// ---------------- kernel 2: GEMM + interleaved top-k, reg-fragment pipelined ----------------
__device__ __forceinline__ void load_B_chunk(unsigned sBu, int buf, int nb, int kc, int t){
  unsigned bbase = sBu + (unsigned)buf * 16384u;
  #pragma unroll
  for (int i = 0; i < 2; i++){
    int id = t + NT*i;
    int r = id >> 3, c = id & 7;
    int fr = nb + r;
    int ok = (fr < NF);
    cpa16(bbase + (unsigned)((r*8 + ((c ^ r) & 7)) * 16),
          g_mb + (size_t)(ok ? fr : 0) * DIM + kc*64 + c*8, ok ? 16 : 0);
  }
}

__global__ void __launch_bounds__(NT, 1) gemm_topk_kernel(){
  extern __shared__ char smem[];
  const unsigned sA_u = (unsigned)__cvta_generic_to_shared(smem);
  const unsigned sBu  = sA_u + SM_B;

  int t = threadIdx.x, lane = t & 31, w = t >> 5;
  int m0 = blockIdx.x * BM;
  int y  = blockIdx.y;
  int t0 = y * TBASE + min(y, 5);
  int ntiles = TBASE + (y < 5 ? 1 : 0);

  // scan identity: 4 threads per row, 32 cols each
  int srow = t & 127;
  int squad = t >> 7;

  float tv[KP]; int ti[KP];
  #pragma unroll
  for (int i = 0; i < KP; i++){ tv[i] = -INFINITY; ti[i] = 0; }
  float tmin = -INFINITY; int minpos = 0;

  // scan one 8-col chunk (one uint4) with hmax2 fast-reject
  auto scan_chunk = [&](int pb, int nb, int kc){
    uint4 d = *(const uint4*)(smem + SM_S + pb*SBUF + srow*SROW + squad*64 + kc*16);
    __nv_bfloat162 v0 = *(__nv_bfloat162*)&d.x;
    __nv_bfloat162 v1 = *(__nv_bfloat162*)&d.y;
    __nv_bfloat162 v2 = *(__nv_bfloat162*)&d.z;
    __nv_bfloat162 v3 = *(__nv_bfloat162*)&d.w;
    __nv_bfloat162 mm = __hmax2(__hmax2(v0, v1), __hmax2(v2, v3));
    float mx = __bfloat162float(__hmax(mm.x, mm.y));
    if (mx > tmin){
      uint32_t word[4] = {d.x, d.y, d.z, d.w};
      int cbase = nb + squad*32 + kc*8;
      #pragma unroll
      for (int h = 0; h < 4; h++){
        float2 f = __bfloat1622float2(*(__nv_bfloat162*)&word[h]);
        int gc0 = cbase + 2*h;
        if (f.x > tmin && gc0 < NF){
          #pragma unroll
          for (int q = 0; q < KP; q++) if (q == minpos){ tv[q] = f.x; ti[q] = gc0; }
          tmin = tv[0]; minpos = 0;
          #pragma unroll
          for (int q = 1; q < KP; q++) if (tv[q] < tmin){ tmin = tv[q]; minpos = q; }
        }
        if (f.y > tmin && gc0 + 1 < NF){
          #pragma unroll
          for (int q = 0; q < KP; q++) if (q == minpos){ tv[q] = f.y; ti[q] = gc0 + 1; }
          tmin = tv[0]; minpos = 0;
          #pragma unroll
          for (int q = 1; q < KP; q++) if (tv[q] < tmin){ tmin = tv[q]; minpos = q; }
        }
      }
    }
  };

  // prologue: A tile + first 3 B stages
  #pragma unroll
  for (int i = 0; i < 8; i++){
    int id = t + NT*i;
    int row = id >> 5, c = id & 31;
    int phys = (c & 24) | ((c ^ row) & 7);
    cpa16(sA_u + (unsigned)((row*32 + phys)*16),
          g_xb + (size_t)(m0 + row)*DIM + c*8, 16);
  }
  load_B_chunk(sBu, 0, (t0 + 0)*BN, 0, t);
  cpa_commit();
  load_B_chunk(sBu, 1, (t0 + 0)*BN, 1, t);
  cpa_commit();
  load_B_chunk(sBu, 2, (t0 + 0)*BN, 2, t);
  cpa_commit();

  int wr = (w >> 2) * 32;     // warp rows [wr, wr+32)
  int wc = (w & 3) * 32;      // warp cols [wc, wc+32)
  int total = ntiles * 4;
  int hi = lane >> 4;
  int lo15 = lane & 15;

  // precompute B smem offsets (kc-invariant): boff[ss][p]
  unsigned boff[4][2];
  #pragma unroll
  for (int ss = 0; ss < 4; ss++){
    #pragma unroll
    for (int p = 0; p < 2; p++){
      int row = wc + 16*p + lo15;
      int c = 2*ss + hi;
      int phys = (c ^ row) & 7;
      boff[ss][p] = (unsigned)((row*8 + phys)*16);
    }
  }
  // precompute A rows
  unsigned arow[2];
  #pragma unroll
  for (int mf = 0; mf < 2; mf++) arow[mf] = (unsigned)(wr + 16*mf + lo15);

  // fragment loader: af[2][4], bv[2][4] for (kc, ss)
  auto frag_load = [&](int kc, int ss, uint32_t af[2][4], uint32_t bv[2][4], unsigned bbase){
    int c = kc*8 + 2*ss + hi;
    #pragma unroll
    for (int mf = 0; mf < 2; mf++){
      int row = arow[mf];
      int phys = (c & 24) | ((c ^ row) & 7);
      ldsm4(af[mf], sA_u + (unsigned)((row*32 + phys)*16));
    }
    #pragma unroll
    for (int p = 0; p < 2; p++){
      uint32_t r[4];
      ldsm4(r, bbase + boff[ss][p]);
      bv[0][2*p] = r[0]; bv[0][2*p+1] = r[1];
      bv[1][2*p] = r[2]; bv[1][2*p+1] = r[3];
    }
  };

  for (int i = 0; i < ntiles; i++){
    float acc[2][4][4];
    #pragma unroll
    for (int mf = 0; mf < 2; mf++)
      #pragma unroll
      for (int nf = 0; nf < 4; nf++)
        #pragma unroll
        for (int q = 0; q < 4; q++) acc[mf][nf][q] = 0.f;

    #pragma unroll
    for (int kc = 0; kc < 4; kc++){
      int s = i*4 + kc;
      cpa_wait<2>();                      // stage-s groups complete (this thread)
      __syncthreads();                    // stage-s data visible; stage s-1 readers done
      int sn = s + 3;
      if (sn < total){
        load_B_chunk(sBu, sn & 3, (t0 + (sn >> 2))*BN, sn & 3, t);
      }
      cpa_commit();

      unsigned bbase = sBu + (unsigned)(s & 3) * 16384u;

      // software-pipelined fragments: load ss+1 while running mma of ss
      uint32_t afb[2][2][4], bvb[2][2][4];
      frag_load(kc, 0, afb[0], bvb[0], bbase);
      #pragma unroll
      for (int ss = 0; ss < 4; ss++){
        int cur = ss & 1;
        if (ss < 3) frag_load(kc, ss + 1, afb[cur ^ 1], bvb[cur ^ 1], bbase);
        if (ss == 0 && i > 0) scan_chunk((i - 1) & 1, (t0 + i - 1)*BN, kc);
        #pragma unroll
        for (int mf = 0; mf < 2; mf++)
          #pragma unroll
          for (int nf = 0; nf < 4; nf++)
            mma16816(acc[mf][nf], afb[cur][mf], bvb[cur][0][nf], bvb[cur][1][nf]);
      }
    }

    // dump sims tile i (bf16) into buffer i&1
    int b = i & 1;
    int r0r = wr + (lane >> 2);
    int c0c = wc + 2*(lane & 3);
    #pragma unroll
    for (int mf = 0; mf < 2; mf++){
      #pragma unroll
      for (int nf = 0; nf < 4; nf++){
        int rr = r0r + 16*mf, cc = c0c + 8*nf;
        __nv_bfloat162 p0 = __floats2bfloat162_rn(acc[mf][nf][0], acc[mf][nf][1]);
        __nv_bfloat162 p1 = __floats2bfloat162_rn(acc[mf][nf][2], acc[mf][nf][3]);
        *(__nv_bfloat162*)(smem + SM_S + b*SBUF + rr*SROW + cc*2) = p0;
        *(__nv_bfloat162*)(smem + SM_S + b*SBUF + (rr+8)*SROW + cc*2) = p1;
      }
    }
  }

  // epilogue: scan last tile (dump must be visible)
  __syncthreads();
  {
    int i = ntiles - 1;
    #pragma unroll
    for (int kc = 0; kc < 4; kc++) scan_chunk(i & 1, (t0 + i)*BN, kc);
  }

  size_t base = (size_t)(m0 + srow) * NCAND + (size_t)y * (4*KP) + (size_t)squad * KP;
  #pragma unroll
  for (int i = 0; i < KP; i++){ g_cval[base + i] = tv[i]; g_cidx[base + i] = ti[i]; }
}

// ---------------- kernel 3: merge + exact rescore + softmax + scatter ----------------
__global__ void __launch_bounds__(128) merge_kernel(const float* __restrict__ mf,
                                                    const int* __restrict__ lab,
                                                    float* __restrict__ out){
  int row = blockIdx.x, t = threadIdx.x, lane = t & 31, w = t >> 5;
  __shared__ float cv[NCAND];
  __shared__ int   ci[NCAND];
  __shared__ float xs[DIM];
  __shared__ float accs[NCLS];
  __shared__ int   selIdx[CSEL];
  __shared__ float ex[CSEL];
  __shared__ float wgt[KSEL]; __shared__ int flab[KSEL];

  for (int j = t; j < NCAND; j += 128){
    cv[j] = g_cval[(size_t)row*NCAND + j];
    ci[j] = g_cidx[(size_t)row*NCAND + j];
  }
  for (int j = t; j < DIM; j += 128) xs[j] = g_xn[row*DIM + j];
  for (int c = t; c < NCLS; c += 128) accs[c] = 0.f;
  __syncthreads();

  if (w == 0){
    for (int it = 0; it < CSEL; it++){
      float bv = -INFINITY; int bp = 0;
      for (int j = lane; j < NCAND; j += 32){
        float c = cv[j];
        if (c > bv){ bv = c; bp = j; }
      }
      #pragma unroll
      for (int o = 16; o; o >>= 1){
        float ov = __shfl_xor_sync(0xffffffffu, bv, o);
        int   op = __shfl_xor_sync(0xffffffffu, bp, o);
        if (ov > bv || (ov == bv && op < bp)){ bv = ov; bp = op; }
      }
      if (lane == 0){ selIdx[it] = ci[bp]; cv[bp] = -INFINITY; }
      __syncwarp();
    }
  }
  __syncthreads();

  for (int rr = 0; rr < CSEL/4; rr++){
    int c = w + 4*rr;
    const float* fr = mf + (size_t)selIdx[c] * DIM;
    float s = 0.f;
    #pragma unroll
    for (int j = 0; j < 8; j++){ int k = lane + 32*j; s += fr[k] * xs[k]; }
    #pragma unroll
    for (int o = 16; o; o >>= 1) s += __shfl_down_sync(0xffffffffu, s, o);
    if (lane == 0) ex[c] = s;
  }
  __syncthreads();

  if (t == 0){
    unsigned um = 0;
    float sval[KSEL]; int sfeat[KSEL];
    for (int it = 0; it < KSEL; it++){
      float bv = -INFINITY; int bc = 0;
      for (int c = 0; c < CSEL; c++){
        if (!((um >> c) & 1u) && ex[c] > bv){ bv = ex[c]; bc = c; }
      }
      um |= 1u << bc;
      sval[it] = bv; sfeat[it] = selIdx[bc];
    }
    float m = sval[0], sum = 0.f;
    for (int i = 0; i < KSEL; i++){ float e = expf((sval[i]-m)/TAUF); wgt[i] = e; sum += e; }
    float inv = 1.f / sum;
    for (int i = 0; i < KSEL; i++){ wgt[i] *= inv; flab[i] = lab[sfeat[i]]; }
    for (int i = 0; i < KSEL; i++) accs[flab[i]] += wgt[i];
  }
  __syncthreads();
  for (int c = t; c < NCLS; c += 128) out[(size_t)row*NCLS + c] = accs[c] * LSCALE;
}

// ---------------- dummy (profiling alignment: gemm at launch position 3) ----------------
__global__ void dummy_kernel(){}

// ---------------- launch ----------------
extern "C" void kernel_launch(void* const* d_in, const int* in_sizes, int n_in,
                              void* d_out, int out_size){
  const float* x    = (const float*)d_in[0];
  const float* mean = (const float*)d_in[1];
  const float* stdv = (const float*)d_in[2];
  const float* mf   = (const float*)d_in[3];
  const int*   lab  = (const int*)d_in[4];
  float* out = (float*)d_out;

  cudaFuncSetAttribute(gemm_topk_kernel, cudaFuncAttributeMaxDynamicSharedMemorySize, SM_TOTAL);

  setup_kernel<<<NQ, DIM>>>(x, mean, stdv, mf);   // pos 0
  dummy_kernel<<<1, 32>>>();                      // pos 1
  dummy_kernel<<<1, 32>>>();                      // pos 2
  gemm_topk_kernel<<<dim3(NQ/BM, NSTRIPE), NT, SM_TOTAL>>>();  // pos 3
  merge_kernel<<<NQ, 128>>>(mf, lab, out);        // pos 4
}